// round 7
// baseline (speedup 1.0000x reference)
#include <cuda_runtime.h>
#include <math.h>

#define NN 192
#define TT 20
#define DH 64
#define DE 32
#define DR 32
#define NB 48
#define NTH 512
#define RPB 4
#define TPR 128

// ---- device scratch (no allocations allowed) ----
__device__ float g_h1[NN*DH], g_h2[NN*DH];         // post-LSTM / post-gcn0 h (cross-block)
__device__ float g_B0[NN*DH], g_B1[NN*DH];         // pre B-parts (cross-block)
__device__ float g_b0v[NN], g_b1v[NN];             // pre b scalars (cross-block)
__device__ float g_acc[4], g_v[3];
__device__ unsigned g_bar[2];                      // memset to 0 each launch
// transposed weights (built once at kernel start)
__device__ float g_wihT[DE*256];                   // [e][r]
__device__ float g_whhT[DH*256];                   // [e][r]
__device__ float g_wABT[2*2*64*64];                // [p][part][k][h]
__device__ float g_wneiT[2*64*64];                 // [p][k][h]

__device__ __forceinline__ void gbar(unsigned& sense) {
    __syncthreads();
    if (threadIdx.x == 0) {
        unsigned want = sense + 1u;
        __threadfence();
        unsigned a = atomicAdd(&g_bar[0], 1u);
        if (a == NB - 1u) {
            g_bar[0] = 0u;
            asm volatile("st.release.gpu.u32 [%0], %1;" :: "l"(&g_bar[1]), "r"(want) : "memory");
        } else {
            unsigned v;
            for (;;) {
                asm volatile("ld.acquire.gpu.u32 %0, [%1];" : "=r"(v) : "l"(&g_bar[1]) : "memory");
                if (v >= want) break;
                __nanosleep(32);
            }
        }
    }
    __syncthreads();
    sense += 1u;
}

__device__ __forceinline__ float wsum(float v) {
#pragma unroll
    for (int o = 16; o; o >>= 1) v += __shfl_xor_sync(0xffffffffu, v, o);
    return v;
}
__device__ __forceinline__ float wmax(float v) {
#pragma unroll
    for (int o = 16; o; o >>= 1) v = fmaxf(v, __shfl_xor_sync(0xffffffffu, v, o));
    return v;
}

__global__ void __launch_bounds__(NTH, 1)
fused_kernel(const float* __restrict__ abs_, const float* __restrict__ norm,
             const float* __restrict__ w_in, const float* __restrict__ b_in,
             const float* __restrict__ w_ih, const float* __restrict__ w_hh,
             const float* __restrict__ b_ih, const float* __restrict__ b_hh,
             const float* __restrict__ w_rel, const float* __restrict__ b_rel,
             const float* __restrict__ w_gate, const float* __restrict__ b_gate,
             const float* __restrict__ w_ar, const float* __restrict__ b_ar,
             const float* __restrict__ w_nei, const float* __restrict__ w_out,
             const float* __restrict__ b_out,
             const int* __restrict__ seq, const int* __restrict__ nei,
             float* __restrict__ out)
{
    // ---- shared state (persistent across the whole scan) ----
    __shared__ float s_wgT[2*DR*DH];          // [p][k][h] Wg[:, :32]^T
    __shared__ __align__(16) float4 s_cst4[2*DR];  // {wrel_x,wrel_y,brel,war_k}
    __shared__ float s_war[2*2*DH];           // [p][part][k] w_ar slices
    __shared__ float s_bcomb[256];            // b_ih + b_hh
    __shared__ float s_bg[2*DH];              // b_gate
    __shared__ float s_bar2[2];               // b_ar
    __shared__ float s_abs[2*NN];             // abs[t] prefetch
    __shared__ unsigned char s_seqb[NN];      // seq[t] > 0
    __shared__ unsigned char s_neib[RPB][NN]; // nei[t,i,:] > 0
    __shared__ float s_gates[RPB][256];       // LSTM gates / msgf scratch
    __shared__ float s_xh[RPB][96];
    __shared__ float s_pos[RPB][NN];
    __shared__ unsigned char s_actb[RPB][NN];
    __shared__ float s_msgM[RPB][4][DH];
    __shared__ float s_hn[RPB][DH];
    __shared__ float s_A[RPB][DH];
    __shared__ float s_a[RPB];
    __shared__ float s_rr[RPB][16];
    __shared__ float s_v1[RPB][4];
    __shared__ float s_h[RPB][DH], s_c[RPB][DH];
    __shared__ float s_og[RPB][DH], s_ctmp[RPB][DH];
    __shared__ int   s_cnt[RPB];

    const int tid  = threadIdx.x;
    const int g    = tid >> 7;            // row group 0..3
    const int ltid = tid & 127;           // 0..127 within group
    const int lane = tid & 31;
    const int w4   = (tid >> 5) & 3;      // warp within group
    const int i    = blockIdx.x * RPB + g;
    const int gtid = blockIdx.x * NTH + tid;
    unsigned sense = 0;

    // ---- one-time smem constant loads ----
    for (int idx = tid; idx < 2*DR*DH; idx += NTH) {
        int p = idx >> 11, r = idx & 2047, k = r >> 6, h = r & 63;
        s_wgT[idx] = w_gate[p*DH*160 + h*160 + k];
    }
    for (int idx = tid; idx < 2*DR; idx += NTH) {
        int p = idx >> 5, k = idx & 31;
        s_cst4[idx] = make_float4(w_rel[p*DR*2 + k*2 + 0], w_rel[p*DR*2 + k*2 + 1],
                                  b_rel[p*DR + k],          w_ar[p*160 + k]);
    }
    for (int idx = tid; idx < 2*2*DH; idx += NTH) {
        int p = idx >> 7, part = (idx >> 6) & 1, k = idx & 63;
        s_war[idx] = w_ar[p*160 + 32 + part*64 + k];
    }
    if (tid < 256) s_bcomb[tid] = b_ih[tid] + b_hh[tid];
    if (tid < 2*DH) s_bg[tid] = b_gate[tid];
    if (tid < 2) s_bar2[tid] = b_ar[tid];
    if (ltid < DH) { s_h[g][ltid] = 0.f; s_c[g][ltid] = 0.f; }

    // ---- one-time global transposes + zero init ----
    for (int idx = gtid; idx < DE*256; idx += NB*NTH) {
        int e = idx >> 8, r = idx & 255;
        g_wihT[idx] = w_ih[r*DE + e];
    }
    for (int idx = gtid; idx < DH*256; idx += NB*NTH) {
        int e = idx >> 8, r = idx & 255;
        g_whhT[idx] = w_hh[r*DH + e];
    }
    for (int idx = gtid; idx < 2*2*64*64; idx += NB*NTH) {
        int h = idx & 63, k = (idx >> 6) & 63, part = (idx >> 12) & 1, p = idx >> 13;
        g_wABT[idx] = w_gate[p*DH*160 + h*160 + 32 + part*64 + k];
    }
    for (int idx = gtid; idx < 2*64*64; idx += NB*NTH) {
        int h = idx & 63, k = (idx >> 6) & 63, p = idx >> 12;
        g_wneiT[idx] = w_nei[p*DH*DH + h*DH + k];
    }
    if (gtid < NN*2) out[(TT-1)*NN*2 + gtid] = 0.f;
    if (blockIdx.x == 0 && tid < 4) g_acc[tid] = 0.f;
    if (blockIdx.x == 0 && tid < 3) g_v[tid] = 0.f;
    gbar(sense);

    for (int t = 0; t < TT-1; t++) {
        //================ Phase A: prefetch + LSTM + pre0 ================
        if (tid < 2*NN) s_abs[tid] = abs_[t*NN*2 + tid];
        if (tid < NN)   s_seqb[tid] = (unsigned char)(seq[t*NN + tid] > 0);
        for (int jj = ltid; jj < NN; jj += TPR)
            s_neib[g][jj] = (unsigned char)(nei[(size_t)t*NN*NN + (size_t)i*NN + jj] > 0);
        if (ltid < DE) {
            float n0 = norm[(t*NN + i)*2 + 0];
            float n1 = norm[(t*NN + i)*2 + 1];
            s_xh[g][ltid] = fmaxf(n0*w_in[ltid*2 + 0] + n1*w_in[ltid*2 + 1] + b_in[ltid], 0.f);
        }
        if (ltid < DH) s_xh[g][32 + ltid] = s_h[g][ltid];
        __syncthreads();
        {
            int r0 = ltid, r1 = ltid + 128;
            float a0 = s_bcomb[r0], a1 = s_bcomb[r1];
#pragma unroll
            for (int e = 0; e < DE; e++) {
                float x = s_xh[g][e];
                a0 += x * g_wihT[e*256 + r0];
                a1 += x * g_wihT[e*256 + r1];
            }
#pragma unroll
            for (int e = 0; e < DH; e++) {
                float x = s_xh[g][32 + e];
                a0 += x * g_whhT[e*256 + r0];
                a1 += x * g_whhT[e*256 + r1];
            }
            s_gates[g][r0] = a0;
            s_gates[g][r1] = a1;
        }
        __syncthreads();
        if (ltid < DH) {
            int h = ltid;
            float ig = 1.f/(1.f+__expf(-s_gates[g][h]));
            float fg = 1.f/(1.f+__expf(-s_gates[g][64 + h]));
            float gg = tanhf(s_gates[g][128 + h]);
            float og = 1.f/(1.f+__expf(-s_gates[g][192 + h]));
            float c1 = fg*s_c[g][h] + ig*gg;
            float h1 = og*tanhf(c1);
            s_ctmp[g][h] = c1;
            s_og[g][h] = og;
            s_hn[g][h] = h1;
            g_h1[i*DH + h] = h1;
        }
        __syncthreads();
        {   // pre0: A-part -> smem, B-part -> global
            int h = ltid & 63, part = ltid >> 6;
            const float* wp = g_wABT + (part*64)*64;   // stage 0
            float acc = 0.f;
#pragma unroll
            for (int k = 0; k < DH; k++) acc += s_hn[g][k]*wp[k*64 + h];
            if (part == 0) s_A[g][h] = acc; else g_B0[i*DH + h] = acc;
        }
        if (w4 == 0) {
            float pa = s_hn[g][lane]*s_war[lane] + s_hn[g][32+lane]*s_war[32+lane];
            pa = wsum(pa);
            if (lane == 0) s_a[g] = pa;
        } else if (w4 == 1) {
            float pb = s_hn[g][lane]*s_war[64+lane] + s_hn[g][32+lane]*s_war[96+lane];
            pb = wsum(pb);
            if (lane == 0) g_b0v[i] = pb;
        }
        gbar(sense);

        //================ Phases B (stage0) and C (stage1) ================
#pragma unroll 1
        for (int STAGE = 0; STAGE < 2; STAGE++) {
            if (STAGE == 1 && blockIdx.x == 0 && tid == 0) {
                const float eps = 1e-6f;
                g_v[0] += g_acc[0] / (g_acc[1]*(float)DH + eps);
                g_v[1] += g_acc[2] / (g_acc[3] + eps);
                g_v[2] += g_acc[1] / (float)NN;
                g_acc[0] = g_acc[1] = g_acc[2] = g_acc[3] = 0.f;
            }
            const float* hcur = STAGE ? g_h2 : g_h1;
            const float* gB   = STAGE ? g_B1 : g_B0;
            const float* gbv  = STAGE ? g_b1v : g_b0v;
            const float barv  = s_bar2[STAGE];
            const float aI    = s_a[g];
            const int   mi    = s_seqb[i];
            const float ax = s_abs[2*i], ay = s_abs[2*i+1];
            const float4* cst = s_cst4 + STAGE*DR;

            if (ltid == 0) s_cnt[g] = 0;
            // entry: scores for j1 = ltid, j2 = 128+ltid (ltid<64)
            const bool has2 = ltid < 64;
            int j1 = ltid, j2 = 128 + ltid;
            float nf1, nf2 = 0.f, sc1, sc2 = -1e30f;
            float cx1, cy1, cx2 = 0.f, cy2 = 0.f;
            {
                nf1 = (s_neib[g][j1] && mi && s_seqb[j1]) ? 1.f : 0.f;
                cx1 = ax - s_abs[2*j1]; cy1 = ay - s_abs[2*j1+1];
                float sc = 0.f;
#pragma unroll
                for (int k = 0; k < DR; k++) {
                    float4 c4 = cst[k];
                    float rv = fmaxf(fmaf(cx1, c4.x, fmaf(cy1, c4.y, c4.z)), 0.f);
                    sc += rv * c4.w;
                }
                sc += aI + __ldcg(&gbv[j1]) + barv;
                sc1 = (nf1 > 0.f) ? sc : -1e9f;
            }
            if (has2) {
                nf2 = (s_neib[g][j2] && mi && s_seqb[j2]) ? 1.f : 0.f;
                cx2 = ax - s_abs[2*j2]; cy2 = ay - s_abs[2*j2+1];
                float sc = 0.f;
#pragma unroll
                for (int k = 0; k < DR; k++) {
                    float4 c4 = cst[k];
                    float rv = fmaxf(fmaf(cx2, c4.x, fmaf(cy2, c4.y, c4.z)), 0.f);
                    sc += rv * c4.w;
                }
                sc += aI + __ldcg(&gbv[j2]) + barv;
                sc2 = (nf2 > 0.f) ? sc : -1e9f;
            }
            // reduce 1: max score, sum neif
            {
                float m = wmax(fmaxf(sc1, sc2));
                float sn = wsum(nf1 + nf2);
                if (lane == 0) { s_rr[g][w4] = m; s_rr[g][4 + w4] = sn; }
            }
            __syncthreads();
            float mm = fmaxf(fmaxf(s_rr[g][0], s_rr[g][1]), fmaxf(s_rr[g][2], s_rr[g][3]));
            float neiRow = s_rr[g][4] + s_rr[g][5] + s_rr[g][6] + s_rr[g][7];
            float e1 = __expf(sc1 - mm);
            float e2 = has2 ? __expf(sc2 - mm) : 0.f;
            // reduce 2: sum e, max e*neif
            {
                float se = wsum(e1 + e2);
                float mn = wmax(fmaxf(e1*nf1, e2*nf2));
                if (lane == 0) { s_rr[g][8 + w4] = se; s_rr[g][12 + w4] = mn; }
            }
            __syncthreads();
            float inv = 1.f / (s_rr[g][8] + s_rr[g][9] + s_rr[g][10] + s_rr[g][11]);
            float maxposRow = fmaxf(fmaxf(s_rr[g][12], s_rr[g][13]),
                                    fmaxf(s_rr[g][14], s_rr[g][15])) * inv;
            s_pos[g][j1] = e1 * inv * nf1;
            if (has2) s_pos[g][j2] = e2 * inv * nf2;
            // active-list compaction (ballot)
            {
                unsigned b1 = __ballot_sync(0xffffffffu, nf1 > 0.f);
                int base = 0;
                if (lane == 0) base = atomicAdd(&s_cnt[g], __popc(b1));
                base = __shfl_sync(0xffffffffu, base, 0);
                if (nf1 > 0.f) s_actb[g][base + __popc(b1 & ((1u << lane) - 1u))] = (unsigned char)j1;
                if (w4 < 2) {
                    unsigned b2 = __ballot_sync(0xffffffffu, nf2 > 0.f);
                    int base2 = 0;
                    if (lane == 0) base2 = atomicAdd(&s_cnt[g], __popc(b2));
                    base2 = __shfl_sync(0xffffffffu, base2, 0);
                    if (nf2 > 0.f) s_actb[g][base2 + __popc(b2 & ((1u << lane) - 1u))] = (unsigned char)j2;
                }
            }
            __syncthreads();
            // gate + message loop over active neighbors
            const float Ai0 = s_A[g][lane]      + s_bg[STAGE*DH + lane];
            const float Ai1 = s_A[g][32 + lane] + s_bg[STAGE*DH + 32 + lane];
            const float* wgS = s_wgT + STAGE*DR*DH;
            float msg0 = 0.f, msg1 = 0.f, v1p = 0.f;
            int cnt = s_cnt[g];
            for (int a = w4; a < cnt; a += 4) {
                int j = s_actb[g][a];
                float pj = s_pos[g][j];
                float cx = ax - s_abs[2*j], cy = ay - s_abs[2*j+1];
                float acc0 = Ai0 + __ldcg(&gB[j*DH + lane]);
                float acc1 = Ai1 + __ldcg(&gB[j*DH + 32 + lane]);
                float hj0 = __ldcg(&hcur[j*DH + lane]);
                float hj1 = __ldcg(&hcur[j*DH + 32 + lane]);
#pragma unroll
                for (int k = 0; k < DR; k++) {
                    float4 c4 = cst[k];
                    float rv = fmaxf(fmaf(cx, c4.x, fmaf(cy, c4.y, c4.z)), 0.f);
                    acc0 += rv * wgS[k*DH + lane];
                    acc1 += rv * wgS[k*DH + 32 + lane];
                }
                float g0 = 1.f/(1.f+__expf(-acc0));
                float g1 = 1.f/(1.f+__expf(-acc1));
                msg0 += pj*g0*hj0;
                msg1 += pj*g1*hj1;
                v1p  += g0 + g1;
            }
            s_msgM[g][w4][lane]      = msg0;
            s_msgM[g][w4][32 + lane] = msg1;
            v1p = wsum(v1p);
            if (lane == 0) s_v1[g][w4] = v1p;
            __syncthreads();
            if (ltid < DH)
                s_gates[g][ltid] = s_msgM[g][0][ltid] + s_msgM[g][1][ltid]
                                 + s_msgM[g][2][ltid] + s_msgM[g][3][ltid];
            __syncthreads();
            if (ltid < DH) {
                int h = ltid;
                float cn = s_ctmp[g][h];
                const float* wn = g_wneiT + STAGE*DH*DH;
#pragma unroll
                for (int k = 0; k < DH; k++) cn += s_gates[g][k]*wn[k*DH + h];
                float hn = s_og[g][h]*tanhf(cn);
                s_hn[g][h] = hn;
                if (STAGE == 0) {
                    s_ctmp[g][h] = cn;
                    g_h2[i*DH + h] = hn;
                } else if (mi) {
                    s_h[g][h] = hn; s_c[g][h] = cn;
                }
            }
            __syncthreads();
            if (STAGE == 0) {
                {   // pre1
                    int h = ltid & 63, part = ltid >> 6;
                    const float* wp = g_wABT + ((2 + part)*64)*64;  // stage 1
                    float acc = 0.f;
#pragma unroll
                    for (int k = 0; k < DH; k++) acc += s_hn[g][k]*wp[k*64 + h];
                    if (part == 0) s_A[g][h] = acc; else g_B1[i*DH + h] = acc;
                }
                if (w4 == 0) {
                    float pa = s_hn[g][lane]*s_war[128+lane] + s_hn[g][32+lane]*s_war[160+lane];
                    pa = wsum(pa);
                    if (lane == 0) s_a[g] = pa;
                } else if (w4 == 1) {
                    float pb = s_hn[g][lane]*s_war[192+lane] + s_hn[g][32+lane]*s_war[224+lane];
                    pb = wsum(pb);
                    if (lane == 0) g_b1v[i] = pb;
                }
                if (ltid == 0) {
                    float gateSum = s_v1[g][0] + s_v1[g][1] + s_v1[g][2] + s_v1[g][3];
                    atomicAdd(&g_acc[0], gateSum);
                    atomicAdd(&g_acc[1], neiRow);
                    atomicAdd(&g_acc[2], maxposRow);
                    atomicAdd(&g_acc[3], neiRow > 0.f ? 1.f : 0.f);
                }
                gbar(sense);
            } else {
                if (ltid < 2) {
                    float o = b_out[ltid];
#pragma unroll
                    for (int k = 0; k < DH; k++) o += s_hn[g][k]*w_out[ltid*DH + k];
                    out[(t*NN + i)*2 + ltid] = mi ? o : 0.f;
                }
            }
        }
        // no barrier between C and next A (A touches only own-row state)
    }

    // final writeback (own rows, own smem)
    const int OFF = TT*NN*2;
    if (ltid < DH) {
        out[OFF + i*DH + ltid]         = s_h[g][ltid];
        out[OFF + NN*DH + i*DH + ltid] = s_c[g][ltid];
    }
    if (blockIdx.x == 0 && tid < 3) out[OFF + 2*NN*DH + tid] = g_v[tid] / (float)TT;
}

extern "C" void kernel_launch(void* const* d_in, const int* in_sizes, int n_in,
                              void* d_out, int out_size) {
    const float* abs_   = (const float*)d_in[0];
    const float* norm   = (const float*)d_in[1];
    const float* w_in   = (const float*)d_in[3];
    const float* b_in   = (const float*)d_in[4];
    const float* w_ih   = (const float*)d_in[5];
    const float* w_hh   = (const float*)d_in[6];
    const float* b_ih   = (const float*)d_in[7];
    const float* b_hh   = (const float*)d_in[8];
    const float* w_rel  = (const float*)d_in[9];
    const float* b_rel  = (const float*)d_in[10];
    const float* w_gate = (const float*)d_in[11];
    const float* b_gate = (const float*)d_in[12];
    const float* w_ar   = (const float*)d_in[13];
    const float* b_ar   = (const float*)d_in[14];
    const float* w_nei  = (const float*)d_in[15];
    const float* w_out  = (const float*)d_in[16];
    const float* b_out  = (const float*)d_in[17];
    const int*   seq    = (const int*)d_in[18];
    const int*   nei    = (const int*)d_in[19];
    float* out = (float*)d_out;

    void* barptr = nullptr;
    cudaGetSymbolAddress(&barptr, g_bar);
    cudaMemsetAsync(barptr, 0, 2*sizeof(unsigned), 0);

    fused_kernel<<<NB, NTH>>>(abs_, norm, w_in, b_in, w_ih, w_hh, b_ih, b_hh,
                              w_rel, b_rel, w_gate, b_gate, w_ar, b_ar,
                              w_nei, w_out, b_out, seq, nei, out);
}

// round 8
// speedup vs baseline: 1.0027x; 1.0027x over previous
#include <cuda_runtime.h>
#include <math.h>

#define NN 192
#define TT 20
#define DH 64
#define DE 32
#define DR 32
#define NB 48
#define NTH 512
#define RPB 4
#define TPR 128

// ---- device scratch (no allocations allowed) ----
__device__ float g_h1[NN*DH], g_h2[NN*DH];         // post-LSTM / post-gcn0 h (cross-block)
__device__ float g_B0[NN*DH], g_B1[NN*DH];         // pre B-parts (cross-block)
__device__ float g_b0v[NN], g_b1v[NN];             // pre b scalars (cross-block)
__device__ float g_acc[4], g_v[3];
__device__ unsigned g_bar[2];                      // memset to 0 each launch
// transposed weights (built once at kernel start)
__device__ float g_wihT[DE*256];                   // [e][r]
__device__ float g_whhT[DH*256];                   // [e][r]
__device__ float g_wABT[2*2*64*64];                // [p][part][k][h]
__device__ float g_wneiT[2*64*64];                 // [p][k][h]

__device__ __forceinline__ void gbar(unsigned& sense) {
    __syncthreads();
    if (threadIdx.x == 0) {
        unsigned want = sense + 1u;
        __threadfence();
        unsigned a = atomicAdd(&g_bar[0], 1u);
        if (a == NB - 1u) {
            g_bar[0] = 0u;
            asm volatile("st.release.gpu.u32 [%0], %1;" :: "l"(&g_bar[1]), "r"(want) : "memory");
        } else {
            unsigned v;
            for (;;) {
                asm volatile("ld.acquire.gpu.u32 %0, [%1];" : "=r"(v) : "l"(&g_bar[1]) : "memory");
                if (v >= want) break;
                __nanosleep(32);
            }
        }
    }
    __syncthreads();
    sense += 1u;
}

__device__ __forceinline__ float wsum(float v) {
#pragma unroll
    for (int o = 16; o; o >>= 1) v += __shfl_xor_sync(0xffffffffu, v, o);
    return v;
}
__device__ __forceinline__ float wmax(float v) {
#pragma unroll
    for (int o = 16; o; o >>= 1) v = fmaxf(v, __shfl_xor_sync(0xffffffffu, v, o));
    return v;
}

__global__ void __launch_bounds__(NTH, 1)
fused_kernel(const float* __restrict__ abs_, const float* __restrict__ norm,
             const float* __restrict__ w_in, const float* __restrict__ b_in,
             const float* __restrict__ w_ih, const float* __restrict__ w_hh,
             const float* __restrict__ b_ih, const float* __restrict__ b_hh,
             const float* __restrict__ w_rel, const float* __restrict__ b_rel,
             const float* __restrict__ w_gate, const float* __restrict__ b_gate,
             const float* __restrict__ w_ar, const float* __restrict__ b_ar,
             const float* __restrict__ w_nei, const float* __restrict__ w_out,
             const float* __restrict__ b_out,
             const int* __restrict__ seq, const int* __restrict__ nei,
             float* __restrict__ out)
{
    // ---- shared state (persistent across the whole scan) ----
    __shared__ float s_wgT[2*DR*DH];          // [p][k][h] Wg[:, :32]^T
    __shared__ __align__(16) float4 s_cst4[2*DR];  // {wrel_x,wrel_y,brel,war_k}
    __shared__ float s_war[2*2*DH];           // [p][part][k] w_ar slices
    __shared__ float s_bcomb[256];            // b_ih + b_hh
    __shared__ float s_bg[2*DH];              // b_gate
    __shared__ float s_bar2[2];               // b_ar
    __shared__ float s_abs[2*NN];             // abs[t] prefetch
    __shared__ unsigned char s_seqb[NN];      // seq[t] > 0
    __shared__ unsigned char s_neib[RPB][NN]; // nei[t,i,:] > 0
    __shared__ float s_gates[RPB][256];       // LSTM gates / msgf scratch
    __shared__ float s_xh[RPB][96];
    __shared__ float s_pos[RPB][NN];
    __shared__ unsigned char s_actb[RPB][NN];
    __shared__ float s_msgM[RPB][4][DH];
    __shared__ float s_hn[RPB][DH];
    __shared__ float s_A[RPB][DH];
    __shared__ float s_a[RPB];
    __shared__ float s_rr[RPB][16];
    __shared__ float s_v1[RPB][4];
    __shared__ float s_h[RPB][DH], s_c[RPB][DH];
    __shared__ float s_og[RPB][DH], s_ctmp[RPB][DH];
    __shared__ int   s_cnt[RPB];

    const int tid  = threadIdx.x;
    const int g    = tid >> 7;            // row group 0..3
    const int ltid = tid & 127;           // 0..127 within group
    const int lane = tid & 31;
    const int w4   = (tid >> 5) & 3;      // warp within group
    const int i    = blockIdx.x * RPB + g;
    const int gtid = blockIdx.x * NTH + tid;
    unsigned sense = 0;

    // ---- one-time smem constant loads ----
    for (int idx = tid; idx < 2*DR*DH; idx += NTH) {
        int p = idx >> 11, r = idx & 2047, k = r >> 6, h = r & 63;
        s_wgT[idx] = w_gate[p*DH*160 + h*160 + k];
    }
    for (int idx = tid; idx < 2*DR; idx += NTH) {
        int p = idx >> 5, k = idx & 31;
        s_cst4[idx] = make_float4(w_rel[p*DR*2 + k*2 + 0], w_rel[p*DR*2 + k*2 + 1],
                                  b_rel[p*DR + k],          w_ar[p*160 + k]);
    }
    for (int idx = tid; idx < 2*2*DH; idx += NTH) {
        int p = idx >> 7, part = (idx >> 6) & 1, k = idx & 63;
        s_war[idx] = w_ar[p*160 + 32 + part*64 + k];
    }
    if (tid < 256) s_bcomb[tid] = b_ih[tid] + b_hh[tid];
    if (tid < 2*DH) s_bg[tid] = b_gate[tid];
    if (tid < 2) s_bar2[tid] = b_ar[tid];
    if (ltid < DH) { s_h[g][ltid] = 0.f; s_c[g][ltid] = 0.f; }

    // ---- one-time global transposes + zero init ----
    for (int idx = gtid; idx < DE*256; idx += NB*NTH) {
        int e = idx >> 8, r = idx & 255;
        g_wihT[idx] = w_ih[r*DE + e];
    }
    for (int idx = gtid; idx < DH*256; idx += NB*NTH) {
        int e = idx >> 8, r = idx & 255;
        g_whhT[idx] = w_hh[r*DH + e];
    }
    for (int idx = gtid; idx < 2*2*64*64; idx += NB*NTH) {
        int h = idx & 63, k = (idx >> 6) & 63, part = (idx >> 12) & 1, p = idx >> 13;
        g_wABT[idx] = w_gate[p*DH*160 + h*160 + 32 + part*64 + k];
    }
    for (int idx = gtid; idx < 2*64*64; idx += NB*NTH) {
        int h = idx & 63, k = (idx >> 6) & 63, p = idx >> 12;
        g_wneiT[idx] = w_nei[p*DH*DH + h*DH + k];
    }
    if (gtid < NN*2) out[(TT-1)*NN*2 + gtid] = 0.f;
    if (blockIdx.x == 0 && tid < 4) g_acc[tid] = 0.f;
    if (blockIdx.x == 0 && tid < 3) g_v[tid] = 0.f;
    gbar(sense);

    for (int t = 0; t < TT-1; t++) {
        //================ Phase A: prefetch + LSTM + pre0 ================
        if (tid < 2*NN) s_abs[tid] = abs_[t*NN*2 + tid];
        if (tid < NN)   s_seqb[tid] = (unsigned char)(seq[t*NN + tid] > 0);
        for (int jj = ltid; jj < NN; jj += TPR)
            s_neib[g][jj] = (unsigned char)(nei[(size_t)t*NN*NN + (size_t)i*NN + jj] > 0);
        if (ltid < DE) {
            float n0 = norm[(t*NN + i)*2 + 0];
            float n1 = norm[(t*NN + i)*2 + 1];
            s_xh[g][ltid] = fmaxf(n0*w_in[ltid*2 + 0] + n1*w_in[ltid*2 + 1] + b_in[ltid], 0.f);
        }
        if (ltid < DH) s_xh[g][32 + ltid] = s_h[g][ltid];
        __syncthreads();
        {
            int r0 = ltid, r1 = ltid + 128;
            float a0 = s_bcomb[r0], a1 = s_bcomb[r1];
#pragma unroll
            for (int e = 0; e < DE; e++) {
                float x = s_xh[g][e];
                a0 += x * g_wihT[e*256 + r0];
                a1 += x * g_wihT[e*256 + r1];
            }
#pragma unroll
            for (int e = 0; e < DH; e++) {
                float x = s_xh[g][32 + e];
                a0 += x * g_whhT[e*256 + r0];
                a1 += x * g_whhT[e*256 + r1];
            }
            s_gates[g][r0] = a0;
            s_gates[g][r1] = a1;
        }
        __syncthreads();
        if (ltid < DH) {
            int h = ltid;
            float ig = 1.f/(1.f+__expf(-s_gates[g][h]));
            float fg = 1.f/(1.f+__expf(-s_gates[g][64 + h]));
            float gg = tanhf(s_gates[g][128 + h]);
            float og = 1.f/(1.f+__expf(-s_gates[g][192 + h]));
            float c1 = fg*s_c[g][h] + ig*gg;
            float h1 = og*tanhf(c1);
            s_ctmp[g][h] = c1;
            s_og[g][h] = og;
            s_hn[g][h] = h1;
            g_h1[i*DH + h] = h1;
        }
        __syncthreads();
        {   // pre0: A-part -> smem, B-part -> global
            int h = ltid & 63, part = ltid >> 6;
            const float* wp = g_wABT + (part*64)*64;   // stage 0
            float acc = 0.f;
#pragma unroll
            for (int k = 0; k < DH; k++) acc += s_hn[g][k]*wp[k*64 + h];
            if (part == 0) s_A[g][h] = acc; else g_B0[i*DH + h] = acc;
        }
        if (w4 == 0) {
            float pa = s_hn[g][lane]*s_war[lane] + s_hn[g][32+lane]*s_war[32+lane];
            pa = wsum(pa);
            if (lane == 0) s_a[g] = pa;
        } else if (w4 == 1) {
            float pb = s_hn[g][lane]*s_war[64+lane] + s_hn[g][32+lane]*s_war[96+lane];
            pb = wsum(pb);
            if (lane == 0) g_b0v[i] = pb;
        }
        gbar(sense);

        //================ Phases B (stage0) and C (stage1) ================
#pragma unroll 1
        for (int STAGE = 0; STAGE < 2; STAGE++) {
            if (STAGE == 1 && blockIdx.x == 0 && tid == 0) {
                const float eps = 1e-6f;
                g_v[0] += g_acc[0] / (g_acc[1]*(float)DH + eps);
                g_v[1] += g_acc[2] / (g_acc[3] + eps);
                g_v[2] += g_acc[1] / (float)NN;
                g_acc[0] = g_acc[1] = g_acc[2] = g_acc[3] = 0.f;
            }
            const float* hcur = STAGE ? g_h2 : g_h1;
            const float* gB   = STAGE ? g_B1 : g_B0;
            const float* gbv  = STAGE ? g_b1v : g_b0v;
            const float barv  = s_bar2[STAGE];
            const float aI    = s_a[g];
            const int   mi    = s_seqb[i];
            const float ax = s_abs[2*i], ay = s_abs[2*i+1];
            const float4* cst = s_cst4 + STAGE*DR;

            if (ltid == 0) s_cnt[g] = 0;
            // entry: scores for j1 = ltid, j2 = 128+ltid (ltid<64)
            const bool has2 = ltid < 64;
            int j1 = ltid, j2 = 128 + ltid;
            float nf1, nf2 = 0.f, sc1, sc2 = -1e30f;
            float cx1, cy1, cx2 = 0.f, cy2 = 0.f;
            {
                nf1 = (s_neib[g][j1] && mi && s_seqb[j1]) ? 1.f : 0.f;
                cx1 = ax - s_abs[2*j1]; cy1 = ay - s_abs[2*j1+1];
                float sc = 0.f;
#pragma unroll
                for (int k = 0; k < DR; k++) {
                    float4 c4 = cst[k];
                    float rv = fmaxf(fmaf(cx1, c4.x, fmaf(cy1, c4.y, c4.z)), 0.f);
                    sc += rv * c4.w;
                }
                sc += aI + __ldcg(&gbv[j1]) + barv;
                sc1 = (nf1 > 0.f) ? sc : -1e9f;
            }
            if (has2) {
                nf2 = (s_neib[g][j2] && mi && s_seqb[j2]) ? 1.f : 0.f;
                cx2 = ax - s_abs[2*j2]; cy2 = ay - s_abs[2*j2+1];
                float sc = 0.f;
#pragma unroll
                for (int k = 0; k < DR; k++) {
                    float4 c4 = cst[k];
                    float rv = fmaxf(fmaf(cx2, c4.x, fmaf(cy2, c4.y, c4.z)), 0.f);
                    sc += rv * c4.w;
                }
                sc += aI + __ldcg(&gbv[j2]) + barv;
                sc2 = (nf2 > 0.f) ? sc : -1e9f;
            }
            // reduce 1: max score, sum neif
            {
                float m = wmax(fmaxf(sc1, sc2));
                float sn = wsum(nf1 + nf2);
                if (lane == 0) { s_rr[g][w4] = m; s_rr[g][4 + w4] = sn; }
            }
            __syncthreads();
            float mm = fmaxf(fmaxf(s_rr[g][0], s_rr[g][1]), fmaxf(s_rr[g][2], s_rr[g][3]));
            float neiRow = s_rr[g][4] + s_rr[g][5] + s_rr[g][6] + s_rr[g][7];
            float e1 = __expf(sc1 - mm);
            float e2 = has2 ? __expf(sc2 - mm) : 0.f;
            // reduce 2: sum e, max e*neif
            {
                float se = wsum(e1 + e2);
                float mn = wmax(fmaxf(e1*nf1, e2*nf2));
                if (lane == 0) { s_rr[g][8 + w4] = se; s_rr[g][12 + w4] = mn; }
            }
            __syncthreads();
            float inv = 1.f / (s_rr[g][8] + s_rr[g][9] + s_rr[g][10] + s_rr[g][11]);
            float maxposRow = fmaxf(fmaxf(s_rr[g][12], s_rr[g][13]),
                                    fmaxf(s_rr[g][14], s_rr[g][15])) * inv;
            s_pos[g][j1] = e1 * inv * nf1;
            if (has2) s_pos[g][j2] = e2 * inv * nf2;
            // active-list compaction (ballot)
            {
                unsigned b1 = __ballot_sync(0xffffffffu, nf1 > 0.f);
                int base = 0;
                if (lane == 0) base = atomicAdd(&s_cnt[g], __popc(b1));
                base = __shfl_sync(0xffffffffu, base, 0);
                if (nf1 > 0.f) s_actb[g][base + __popc(b1 & ((1u << lane) - 1u))] = (unsigned char)j1;
                if (w4 < 2) {
                    unsigned b2 = __ballot_sync(0xffffffffu, nf2 > 0.f);
                    int base2 = 0;
                    if (lane == 0) base2 = atomicAdd(&s_cnt[g], __popc(b2));
                    base2 = __shfl_sync(0xffffffffu, base2, 0);
                    if (nf2 > 0.f) s_actb[g][base2 + __popc(b2 & ((1u << lane) - 1u))] = (unsigned char)j2;
                }
            }
            __syncthreads();
            // gate + message loop over active neighbors
            const float Ai0 = s_A[g][lane]      + s_bg[STAGE*DH + lane];
            const float Ai1 = s_A[g][32 + lane] + s_bg[STAGE*DH + 32 + lane];
            const float* wgS = s_wgT + STAGE*DR*DH;
            float msg0 = 0.f, msg1 = 0.f, v1p = 0.f;
            int cnt = s_cnt[g];
            for (int a = w4; a < cnt; a += 4) {
                int j = s_actb[g][a];
                float pj = s_pos[g][j];
                float cx = ax - s_abs[2*j], cy = ay - s_abs[2*j+1];
                float acc0 = Ai0 + __ldcg(&gB[j*DH + lane]);
                float acc1 = Ai1 + __ldcg(&gB[j*DH + 32 + lane]);
                float hj0 = __ldcg(&hcur[j*DH + lane]);
                float hj1 = __ldcg(&hcur[j*DH + 32 + lane]);
#pragma unroll
                for (int k = 0; k < DR; k++) {
                    float4 c4 = cst[k];
                    float rv = fmaxf(fmaf(cx, c4.x, fmaf(cy, c4.y, c4.z)), 0.f);
                    acc0 += rv * wgS[k*DH + lane];
                    acc1 += rv * wgS[k*DH + 32 + lane];
                }
                float g0 = 1.f/(1.f+__expf(-acc0));
                float g1 = 1.f/(1.f+__expf(-acc1));
                msg0 += pj*g0*hj0;
                msg1 += pj*g1*hj1;
                v1p  += g0 + g1;
            }
            s_msgM[g][w4][lane]      = msg0;
            s_msgM[g][w4][32 + lane] = msg1;
            v1p = wsum(v1p);
            if (lane == 0) s_v1[g][w4] = v1p;
            __syncthreads();
            if (ltid < DH)
                s_gates[g][ltid] = s_msgM[g][0][ltid] + s_msgM[g][1][ltid]
                                 + s_msgM[g][2][ltid] + s_msgM[g][3][ltid];
            __syncthreads();
            if (ltid < DH) {
                int h = ltid;
                float cn = s_ctmp[g][h];
                const float* wn = g_wneiT + STAGE*DH*DH;
#pragma unroll
                for (int k = 0; k < DH; k++) cn += s_gates[g][k]*wn[k*DH + h];
                float hn = s_og[g][h]*tanhf(cn);
                s_hn[g][h] = hn;
                if (STAGE == 0) {
                    s_ctmp[g][h] = cn;
                    g_h2[i*DH + h] = hn;
                } else if (mi) {
                    s_h[g][h] = hn; s_c[g][h] = cn;
                }
            }
            __syncthreads();
            if (STAGE == 0) {
                {   // pre1
                    int h = ltid & 63, part = ltid >> 6;
                    const float* wp = g_wABT + ((2 + part)*64)*64;  // stage 1
                    float acc = 0.f;
#pragma unroll
                    for (int k = 0; k < DH; k++) acc += s_hn[g][k]*wp[k*64 + h];
                    if (part == 0) s_A[g][h] = acc; else g_B1[i*DH + h] = acc;
                }
                if (w4 == 0) {
                    float pa = s_hn[g][lane]*s_war[128+lane] + s_hn[g][32+lane]*s_war[160+lane];
                    pa = wsum(pa);
                    if (lane == 0) s_a[g] = pa;
                } else if (w4 == 1) {
                    float pb = s_hn[g][lane]*s_war[192+lane] + s_hn[g][32+lane]*s_war[224+lane];
                    pb = wsum(pb);
                    if (lane == 0) g_b1v[i] = pb;
                }
                if (ltid == 0) {
                    float gateSum = s_v1[g][0] + s_v1[g][1] + s_v1[g][2] + s_v1[g][3];
                    atomicAdd(&g_acc[0], gateSum);
                    atomicAdd(&g_acc[1], neiRow);
                    atomicAdd(&g_acc[2], maxposRow);
                    atomicAdd(&g_acc[3], neiRow > 0.f ? 1.f : 0.f);
                }
                gbar(sense);
            } else {
                if (ltid < 2) {
                    float o = b_out[ltid];
#pragma unroll
                    for (int k = 0; k < DH; k++) o += s_hn[g][k]*w_out[ltid*DH + k];
                    out[(t*NN + i)*2 + ltid] = mi ? o : 0.f;
                }
            }
        }
        // no barrier between C and next A (A touches only own-row state)
    }

    // final writeback (own rows, own smem)
    const int OFF = TT*NN*2;
    if (ltid < DH) {
        out[OFF + i*DH + ltid]         = s_h[g][ltid];
        out[OFF + NN*DH + i*DH + ltid] = s_c[g][ltid];
    }
    if (blockIdx.x == 0 && tid < 3) out[OFF + 2*NN*DH + tid] = g_v[tid] / (float)TT;
}

extern "C" void kernel_launch(void* const* d_in, const int* in_sizes, int n_in,
                              void* d_out, int out_size) {
    const float* abs_   = (const float*)d_in[0];
    const float* norm   = (const float*)d_in[1];
    const float* w_in   = (const float*)d_in[3];
    const float* b_in   = (const float*)d_in[4];
    const float* w_ih   = (const float*)d_in[5];
    const float* w_hh   = (const float*)d_in[6];
    const float* b_ih   = (const float*)d_in[7];
    const float* b_hh   = (const float*)d_in[8];
    const float* w_rel  = (const float*)d_in[9];
    const float* b_rel  = (const float*)d_in[10];
    const float* w_gate = (const float*)d_in[11];
    const float* b_gate = (const float*)d_in[12];
    const float* w_ar   = (const float*)d_in[13];
    const float* b_ar   = (const float*)d_in[14];
    const float* w_nei  = (const float*)d_in[15];
    const float* w_out  = (const float*)d_in[16];
    const float* b_out  = (const float*)d_in[17];
    const int*   seq    = (const int*)d_in[18];
    const int*   nei    = (const int*)d_in[19];
    float* out = (float*)d_out;

    void* barptr = nullptr;
    cudaGetSymbolAddress(&barptr, g_bar);
    cudaMemsetAsync(barptr, 0, 2*sizeof(unsigned), 0);

    fused_kernel<<<NB, NTH>>>(abs_, norm, w_in, b_in, w_ih, w_hh, b_ih, b_hh,
                              w_rel, b_rel, w_gate, b_gate, w_ar, b_ar,
                              w_nei, w_out, b_out, seq, nei, out);
}